// round 11
// baseline (speedup 1.0000x reference)
#include <cuda_runtime.h>
#include <cstdint>

#define POOL 14
#define IMG_H 200
#define IMG_W 200
#define IMG_C 1024
#define NUM_ROIS 512

#define NCHUNK 4                       // 256-ch slices -> 41MB image slice, L2-resident
#define CHUNK_FLOATS (IMG_C / NCHUNK)  // 256 floats = 1KB per cell-chunk
#define LANES_PER_CELL 8               // each lane: 4 segments of 32B (8 floats)
#define CELLS_PER_BLOCK 32
#define THREADS (LANES_PER_CELL * CELLS_PER_BLOCK)  // 256

// ---- packed f32x2 helpers (sm_103a) ----
__device__ __forceinline__ unsigned long long pk2(float a, float b) {
    unsigned long long r;
    asm("mov.b64 %0, {%1, %2};" : "=l"(r) : "f"(a), "f"(b));
    return r;
}
__device__ __forceinline__ unsigned long long mul2(unsigned long long a, unsigned long long b) {
    unsigned long long r;
    asm("mul.rn.f32x2 %0, %1, %2;" : "=l"(r) : "l"(a), "l"(b));
    return r;
}
__device__ __forceinline__ unsigned long long fma2(unsigned long long a, unsigned long long b,
                                                   unsigned long long c) {
    unsigned long long r;
    asm("fma.rn.f32x2 %0, %1, %2, %3;" : "=l"(r) : "l"(a), "l"(b), "l"(c));
    return r;
}

// 256-bit global load: 4x packed f32x2 = 8 floats = 32B.
__device__ __forceinline__ void ldg256(const float* p,
                                       unsigned long long& r0, unsigned long long& r1,
                                       unsigned long long& r2, unsigned long long& r3) {
    asm volatile("ld.global.nc.v4.b64 {%0,%1,%2,%3}, [%4];"
                 : "=l"(r0), "=l"(r1), "=l"(r2), "=l"(r3) : "l"(p));
}

// 256-bit streaming store (.cs: evict-first, protects the L2 image slice).
__device__ __forceinline__ void stg256_cs(float* p,
                                          unsigned long long r0, unsigned long long r1,
                                          unsigned long long r2, unsigned long long r3) {
    asm volatile("st.global.cs.v4.b64 [%0], {%1,%2,%3,%4};"
                 :: "l"(p), "l"(r0), "l"(r1), "l"(r2), "l"(r3) : "memory");
}

// grid = (cells/32, NCHUNK). Chunk-outer keeps each 41MB channel slice
// L2-resident (~472MB DRAM traffic, measured). Wide 256-bit LDG/STG minimize
// LSU issue (R10); two-phase lerp + launch_bounds(256,5) cap regs ~51 so
// occupancy recovers to R5 levels (R10's 74 regs / 30% occ was the regression).
__global__ void __launch_bounds__(THREADS, 5)
roi_resize_kernel(const float* __restrict__ img,
                  const int* __restrict__ rois,
                  float* __restrict__ out)
{
    const int cell_local = threadIdx.x >> 3;        // 0..31
    const int c          = threadIdx.x & 7;         // lane within cell

    const int idx  = blockIdx.x * CELLS_PER_BLOCK + cell_local;  // 0..100351
    const int roi  = idx / (POOL * POOL);
    const int cell = idx - roi * (POOL * POOL);
    const int py   = cell / POOL;
    const int px   = cell - py * POOL;

    const int chunk_off = blockIdx.y * CHUNK_FLOATS;

    const int4 box = reinterpret_cast<const int4*>(rois)[roi];
    const int bx = box.x, by = box.y, bw = box.z, bh = box.w;

    // Match reference math: fraction from UNclipped floor.
    const float sy = (float)py * ((float)bh / (float)POOL);
    const float sx = (float)px * ((float)bw / (float)POOL);
    const int y0 = (int)floorf(sy);
    const int x0 = (int)floorf(sx);
    const float wy = sy - (float)y0;
    const float wx = sx - (float)x0;

    const int y0c = min(max(y0, 0), bh - 1);
    const int y1c = min(max(y0 + 1, 0), bh - 1);
    const int x0c = min(max(x0, 0), bw - 1);
    const int x1c = min(max(x0 + 1, 0), bw - 1);

    const int iy0 = by + y0c;
    const int iy1 = by + y1c;
    const int ix0 = bx + x0c;
    const int ix1 = bx + x1c;

    const unsigned long long wx2   = pk2(wx, wx);
    const unsigned long long omwx2 = pk2(1.0f - wx, 1.0f - wx);
    const unsigned long long wy2   = pk2(wy, wy);
    const unsigned long long omwy2 = pk2(1.0f - wy, 1.0f - wy);

    // Base covers this chunk; lane offset folded in once.
    const float* base = img + chunk_off + c * 8;
    const float* __restrict__ p00 = base + ((size_t)iy0 * IMG_W + ix0) * IMG_C;
    const float* __restrict__ p01 = base + ((size_t)iy0 * IMG_W + ix1) * IMG_C;
    const float* __restrict__ p10 = base + ((size_t)iy1 * IMG_W + ix0) * IMG_C;
    const float* __restrict__ p11 = base + ((size_t)iy1 * IMG_W + ix1) * IMG_C;

    float* __restrict__ o = out + (size_t)idx * IMG_C + chunk_off + c * 8;

    // 4 segments of 64 floats; lane handles 8 contiguous floats per segment.
    // Two-phase lerp per segment keeps peak live corner regs at 16 (not 32).
#pragma unroll
    for (int s = 0; s < 4; s++) {
        const int foff = s * 64;   // float offset of this segment

        // Phase 1: top row -> top = g00*(1-wx) + g01*wx
        unsigned long long g0a, g0b, g0c, g0d;
        unsigned long long g1a, g1b, g1c, g1d;
        ldg256(p00 + foff, g0a, g0b, g0c, g0d);
        ldg256(p01 + foff, g1a, g1b, g1c, g1d);
        unsigned long long t0 = fma2(g1a, wx2, mul2(g0a, omwx2));
        unsigned long long t1 = fma2(g1b, wx2, mul2(g0b, omwx2));
        unsigned long long t2 = fma2(g1c, wx2, mul2(g0c, omwx2));
        unsigned long long t3 = fma2(g1d, wx2, mul2(g0d, omwx2));

        // Phase 2: bottom row -> bot, then r = top*(1-wy) + bot*wy
        ldg256(p10 + foff, g0a, g0b, g0c, g0d);
        ldg256(p11 + foff, g1a, g1b, g1c, g1d);
        unsigned long long b0 = fma2(g1a, wx2, mul2(g0a, omwx2));
        unsigned long long b1 = fma2(g1b, wx2, mul2(g0b, omwx2));
        unsigned long long b2 = fma2(g1c, wx2, mul2(g0c, omwx2));
        unsigned long long b3 = fma2(g1d, wx2, mul2(g0d, omwx2));

        const unsigned long long r0 = fma2(b0, wy2, mul2(t0, omwy2));
        const unsigned long long r1 = fma2(b1, wy2, mul2(t1, omwy2));
        const unsigned long long r2 = fma2(b2, wy2, mul2(t2, omwy2));
        const unsigned long long r3 = fma2(b3, wy2, mul2(t3, omwy2));

        stg256_cs(o + foff, r0, r1, r2, r3);
    }
}

extern "C" void kernel_launch(void* const* d_in, const int* in_sizes, int n_in,
                              void* d_out, int out_size)
{
    const float* img  = (const float*)d_in[0];
    const int*   rois = (const int*)d_in[1];
    if (in_sizes[0] == NUM_ROIS * 4) {  // defensive: swapped order
        rois = (const int*)d_in[0];
        img  = (const float*)d_in[1];
    }
    float* out = (float*)d_out;

    dim3 grid((NUM_ROIS * POOL * POOL) / CELLS_PER_BLOCK, NCHUNK);  // (3136, 4)
    roi_resize_kernel<<<grid, THREADS>>>(img, rois, out);
}

// round 12
// speedup vs baseline: 1.1297x; 1.1297x over previous
#include <cuda_runtime.h>
#include <cstdint>

#define POOL 14
#define IMG_H 200
#define IMG_W 200
#define IMG_C 1024
#define NUM_ROIS 512

#define NCHUNK 4                       // 256-ch slices -> 41MB image slice, L2-resident
#define CHUNK_FLOATS (IMG_C / NCHUNK)  // 256 floats per cell-chunk
#define LANES_PER_CELL 16
#define CELLS_PER_BLOCK 16
#define THREADS (LANES_PER_CELL * CELLS_PER_BLOCK)  // 256

typedef unsigned long long u64;

// ---- packed f32x2 helpers (sm_103a) ----
__device__ __forceinline__ u64 pk2(float a, float b) {
    u64 r;
    asm("mov.b64 %0, {%1, %2};" : "=l"(r) : "f"(a), "f"(b));
    return r;
}
__device__ __forceinline__ u64 mul2(u64 a, u64 b) {
    u64 r;
    asm("mul.rn.f32x2 %0, %1, %2;" : "=l"(r) : "l"(a), "l"(b));
    return r;
}
__device__ __forceinline__ u64 fma2(u64 a, u64 b, u64 c) {
    u64 r;
    asm("fma.rn.f32x2 %0, %1, %2, %3;" : "=l"(r) : "l"(a), "l"(b), "l"(c));
    return r;
}

// 128-bit L2-only load (bypasses L1 allocation; gathers have ~no L1 reuse).
// Returns 2x packed f32x2 directly — no repacking movs.
__device__ __forceinline__ void ldg128_cg(const float* p, u64& lo, u64& hi) {
    asm volatile("ld.global.cg.v2.b64 {%0,%1}, [%2];" : "=l"(lo), "=l"(hi) : "l"(p));
}

// 128-bit streaming store (evict-first: protects the L2-resident image slice).
__device__ __forceinline__ void stg128_cs(float* p, u64 lo, u64 hi) {
    asm volatile("st.global.cs.v2.b64 [%0], {%1,%2};" :: "l"(p), "l"(lo), "l"(hi) : "memory");
}

// grid = (cells/16, NCHUNK). R5's proven schedule: chunk-outer keeps each
// 41MB channel slice L2-resident (~472MB DRAM). Edits vs R5: L2-only (.cg)
// reads remove the L1 fill cost; zero-weight corner loads (wy==0 / wx==0)
// are skipped entirely (bit-exact: reference multiplies them by 0).
__global__ void __launch_bounds__(THREADS, 5)
roi_resize_kernel(const float* __restrict__ img,
                  const int* __restrict__ rois,
                  float* __restrict__ out)
{
    const int cell_local = threadIdx.x >> 4;        // 0..15
    const int c          = threadIdx.x & 15;        // float4 lane within cell

    const int idx  = blockIdx.x * CELLS_PER_BLOCK + cell_local;  // 0..100351
    const int roi  = idx / (POOL * POOL);
    const int cell = idx - roi * (POOL * POOL);
    const int py   = cell / POOL;
    const int px   = cell - py * POOL;

    const int chunk_off = blockIdx.y * CHUNK_FLOATS;

    const int4 box = reinterpret_cast<const int4*>(rois)[roi];
    const int bx = box.x, by = box.y, bw = box.z, bh = box.w;

    // Match reference math: fraction from UNclipped floor.
    const float sy = (float)py * ((float)bh / (float)POOL);
    const float sx = (float)px * ((float)bw / (float)POOL);
    const int y0 = (int)floorf(sy);
    const int x0 = (int)floorf(sx);
    const float wy = sy - (float)y0;
    const float wx = sx - (float)x0;

    const bool need_x1 = (wx != 0.0f);   // right corners carry weight
    const bool need_y1 = (wy != 0.0f);   // bottom corners carry weight
    const bool need_xy = need_x1 && need_y1;

    const int y0c = min(max(y0, 0), bh - 1);
    const int y1c = min(max(y0 + 1, 0), bh - 1);
    const int x0c = min(max(x0, 0), bw - 1);
    const int x1c = min(max(x0 + 1, 0), bw - 1);

    const int iy0 = by + y0c;
    const int iy1 = by + y1c;
    const int ix0 = bx + x0c;
    const int ix1 = bx + x1c;

    const u64 wx2   = pk2(wx, wx);
    const u64 omwx2 = pk2(1.0f - wx, 1.0f - wx);
    const u64 wy2   = pk2(wy, wy);
    const u64 omwy2 = pk2(1.0f - wy, 1.0f - wy);

    const float* base = img + chunk_off;
    const float* __restrict__ p00 = base + ((size_t)iy0 * IMG_W + ix0) * IMG_C;
    const float* __restrict__ p01 = base + ((size_t)iy0 * IMG_W + ix1) * IMG_C;
    const float* __restrict__ p10 = base + ((size_t)iy1 * IMG_W + ix0) * IMG_C;
    const float* __restrict__ p11 = base + ((size_t)iy1 * IMG_W + ix1) * IMG_C;

    float* __restrict__ o = out + (size_t)idx * IMG_C + chunk_off;

    // x-lerp of one packed pair
#define XLERP(g0, g1) fma2(g1, wx2, mul2(g0, omwx2))

    // Two batches (R5 structure): each batch covers float offsets
    // [f0, f0+16) and [f1, f1+16); up to 8 front-batched 128-bit loads.
#pragma unroll
    for (int h = 0; h < 2; h++) {
        const int f0 = (c + h * 32) * 4;
        const int f1 = f0 + 64;

        u64 a00l, a00h, b00l, b00h;
        ldg128_cg(p00 + f0, a00l, a00h);
        ldg128_cg(p00 + f1, b00l, b00h);

        u64 a01l = 0, a01h = 0, b01l = 0, b01h = 0;
        if (need_x1) {
            ldg128_cg(p01 + f0, a01l, a01h);
            ldg128_cg(p01 + f1, b01l, b01h);
        }
        u64 a10l = 0, a10h = 0, b10l = 0, b10h = 0;
        if (need_y1) {
            ldg128_cg(p10 + f0, a10l, a10h);
            ldg128_cg(p10 + f1, b10l, b10h);
        }
        u64 a11l = 0, a11h = 0, b11l = 0, b11h = 0;
        if (need_xy) {
            ldg128_cg(p11 + f0, a11l, a11h);
            ldg128_cg(p11 + f1, b11l, b11h);
        }

        // top row x-lerp (or passthrough when wx==0)
        const u64 tal = need_x1 ? XLERP(a00l, a01l) : a00l;
        const u64 tah = need_x1 ? XLERP(a00h, a01h) : a00h;
        const u64 tbl = need_x1 ? XLERP(b00l, b01l) : b00l;
        const u64 tbh = need_x1 ? XLERP(b00h, b01h) : b00h;

        // bottom row x-lerp (or passthroughs when weights are 0)
        const u64 bal = need_y1 ? (need_x1 ? XLERP(a10l, a11l) : a10l) : tal;
        const u64 bah = need_y1 ? (need_x1 ? XLERP(a10h, a11h) : a10h) : tah;
        const u64 bbl = need_y1 ? (need_x1 ? XLERP(b10l, b11l) : b10l) : tbl;
        const u64 bbh = need_y1 ? (need_x1 ? XLERP(b10h, b11h) : b10h) : tbh;

        // y-lerp (exact: when wy==0, bot==top so r==top)
        const u64 ral = fma2(bal, wy2, mul2(tal, omwy2));
        const u64 rah = fma2(bah, wy2, mul2(tah, omwy2));
        const u64 rbl = fma2(bbl, wy2, mul2(tbl, omwy2));
        const u64 rbh = fma2(bbh, wy2, mul2(tbh, omwy2));

        stg128_cs(o + f0, ral, rah);
        stg128_cs(o + f1, rbl, rbh);
    }
#undef XLERP
}

extern "C" void kernel_launch(void* const* d_in, const int* in_sizes, int n_in,
                              void* d_out, int out_size)
{
    const float* img  = (const float*)d_in[0];
    const int*   rois = (const int*)d_in[1];
    if (in_sizes[0] == NUM_ROIS * 4) {  // defensive: swapped order
        rois = (const int*)d_in[0];
        img  = (const float*)d_in[1];
    }
    float* out = (float*)d_out;

    dim3 grid((NUM_ROIS * POOL * POOL) / CELLS_PER_BLOCK, NCHUNK);  // (6272, 4)
    roi_resize_kernel<<<grid, THREADS>>>(img, rois, out);
}